// round 1
// baseline (speedup 1.0000x reference)
#include <cuda_runtime.h>
#include <math.h>

#define NG 4096
#define DQ 512
#define MS 32
#define TK 3
#define ROWP 33          // padded row stride (bank-conflict-free column gather)
#define NTHREADS 256

// Shared layout (floats):
//   Ws   [DQ * ROWP]      = 16896
//   qs   [DQ]             =   512
//   red  [8 * 32]         =   256
//   bval [TK]             =     3
//   bidx [TK] (as int)    =     3  (+2 pad)
#define SM_WS    0
#define SM_QS    (DQ * ROWP)
#define SM_RED   (SM_QS + DQ)
#define SM_BVAL  (SM_RED + 256)
#define SM_BIDX  (SM_BVAL + TK)
#define SM_FLOATS (SM_BIDX + TK + 2)

__global__ __launch_bounds__(NTHREADS, 3)
void cgm_kernel(const float* __restrict__ q,
                const float* __restrict__ W,
                const float* __restrict__ temp_logit,
                const float* __restrict__ shift_mag,
                float* __restrict__ out,
                int write_aux)
{
    extern __shared__ float sm[];
    float* Ws   = sm + SM_WS;
    float* qs   = sm + SM_QS;
    float* red  = sm + SM_RED;
    float* bval = sm + SM_BVAL;
    int*   bidx = (int*)(sm + SM_BIDX);

    const int g   = blockIdx.x;
    const int tid = threadIdx.x;

    // ---- Pass A: stage W[g] (512x32 fp32 = 64KB) into padded SMEM ----
    // 4096 float4 loads / 256 threads = 16 per thread, fully coalesced.
    const float4* Wg = (const float4*)(W + (size_t)g * DQ * MS);
    #pragma unroll
    for (int it = 0; it < 16; it++) {
        int i4 = tid + it * NTHREADS;
        float4 v = Wg[i4];
        int fi = i4 << 2;          // float index within tile
        int d  = fi >> 5;          // /32
        int m  = fi & 31;
        float* p = &Ws[d * ROWP + m];
        p[0] = v.x; p[1] = v.y; p[2] = v.z; p[3] = v.w;
    }
    // q[g] into SMEM (2 loads/thread)
    qs[tid]            = q[(size_t)g * DQ + tid];
    qs[tid + NTHREADS] = q[(size_t)g * DQ + tid + NTHREADS];
    __syncthreads();

    // ---- Pass B: att[m] = sum_d q[d] * W[d][m] ----
    // thread (m = tid&31, p = tid>>5) accumulates 64 d-values.
    {
        int m = tid & 31;
        int p = tid >> 5;
        int d0 = p * 64;
        float acc = 0.f;
        #pragma unroll 8
        for (int d = 0; d < 64; d++) {
            acc = fmaf(qs[d0 + d], Ws[(d0 + d) * ROWP + m], acc);
        }
        red[p * 32 + m] = acc;
    }
    __syncthreads();

    // ---- Warp 0: finalize att, softmax, top-3 ----
    if (tid < 32) {
        float att = 0.f;
        #pragma unroll
        for (int p = 0; p < 8; p++) att += red[p * 32 + tid];

        float tl = temp_logit[g];
        float base = 1.f / (1.f + __expf(-tl)) * 0.6f + 0.2f;
        float temp = base / (1.f + shift_mag[0]);
        float s = att / (temp + 1e-8f);

        // softmax over the 32 lanes
        float mx = s;
        #pragma unroll
        for (int o = 16; o > 0; o >>= 1)
            mx = fmaxf(mx, __shfl_xor_sync(0xffffffffu, mx, o));
        float e = __expf(s - mx);
        float ssum = e;
        #pragma unroll
        for (int o = 16; o > 0; o >>= 1)
            ssum += __shfl_xor_sync(0xffffffffu, ssum, o);
        float pr = e / ssum;

        // top-3 (descending; ties -> lowest index, matching jax.lax.top_k)
        float v = pr;
        int   id = tid;
        #pragma unroll
        for (int k = 0; k < TK; k++) {
            float bv = v;
            int   bi = id;
            #pragma unroll
            for (int o = 16; o > 0; o >>= 1) {
                float ov = __shfl_xor_sync(0xffffffffu, bv, o);
                int   oi = __shfl_xor_sync(0xffffffffu, bi, o);
                if (ov > bv || (ov == bv && oi < bi)) { bv = ov; bi = oi; }
            }
            if (tid == 0) { bval[k] = bv; bidx[k] = bi; }
            if (id == bi) v = -INFINITY;   // remove winner
        }
    }
    __syncthreads();

    // ---- Pass C: retrieved[d] = sum_k vals[k] * W[d][idx[k]] ----
    float v0 = bval[0], v1 = bval[1], v2 = bval[2];
    int   i0 = bidx[0], i1 = bidx[1], i2 = bidx[2];
    float* outg = out + (size_t)g * DQ;
    #pragma unroll
    for (int r = 0; r < 2; r++) {
        int d = tid + r * NTHREADS;
        const float* row = &Ws[d * ROWP];
        outg[d] = v0 * row[i0] + v1 * row[i1] + v2 * row[i2];
    }

    // ---- Aux outputs (idx, vals) in tuple order after retrieved ----
    if (write_aux && tid < TK) {
        float* out_idx  = out + (size_t)NG * DQ;
        float* out_vals = out_idx + (size_t)NG * TK;
        out_idx[(size_t)g * TK + tid]  = (float)bidx[tid];
        out_vals[(size_t)g * TK + tid] = bval[tid];
    }
}

extern "C" void kernel_launch(void* const* d_in, const int* in_sizes, int n_in,
                              void* d_out, int out_size)
{
    const float* q     = (const float*)d_in[0];
    const float* W     = (const float*)d_in[1];
    const float* tl    = (const float*)d_in[2];
    const float* shift = (const float*)d_in[3];
    float* out = (float*)d_out;

    int write_aux = (out_size >= NG * DQ + 2 * NG * TK) ? 1 : 0;

    size_t smem = SM_FLOATS * sizeof(float);
    cudaFuncSetAttribute(cgm_kernel, cudaFuncAttributeMaxDynamicSharedMemorySize, (int)smem);

    cgm_kernel<<<NG, NTHREADS, smem>>>(q, W, tl, shift, out, write_aux);
}

// round 3
// speedup vs baseline: 1.1122x; 1.1122x over previous
#include <cuda_runtime.h>
#include <math.h>

#define NG 4096
#define DQ 512
#define MS 32
#define TK 3
#define NTHREADS 256

__global__ __launch_bounds__(NTHREADS, 4)
void cgm_kernel(const float* __restrict__ q,
                const float* __restrict__ W,
                const float* __restrict__ temp_logit,
                const float* __restrict__ shift_mag,
                float* __restrict__ out,
                int write_aux)
{
    __shared__ float qs[DQ];
    __shared__ float red[8 * 32];     // 8 warps x 32 att slots
    __shared__ float bval[TK];
    __shared__ int   bidx[TK];

    const int g    = blockIdx.x;
    const int tid  = threadIdx.x;
    const int lane = tid & 31;
    const int wrp  = tid >> 5;

    // ---- stage q (2 coalesced loads/thread) ----
    qs[tid]            = q[(size_t)g * DQ + tid];
    qs[tid + NTHREADS] = q[(size_t)g * DQ + tid + NTHREADS];
    __syncthreads();

    // ---- Pass A+B fused: stream W[g], accumulate att partials in registers ----
    // i4 = tid + it*256 -> float idx fi = 4*i4 -> d = i4>>3, m = 4*(i4&7).
    // (i4 & 7) == (tid & 7) for all it, so each thread owns a fixed m-chunk.
    const float4* __restrict__ Wg = (const float4*)(W + (size_t)g * DQ * MS);
    const int dbase = tid >> 3;          // 0..31
    float a0 = 0.f, a1 = 0.f, a2 = 0.f, a3 = 0.f;
    #pragma unroll
    for (int it = 0; it < 16; it++) {
        float4 v = Wg[tid + it * NTHREADS];
        float qd = qs[dbase + it * 32];
        a0 = fmaf(qd, v.x, a0);
        a1 = fmaf(qd, v.y, a1);
        a2 = fmaf(qd, v.z, a2);
        a3 = fmaf(qd, v.w, a3);
    }

    // ---- reduce partials: lanes with same (lane&7) share an m-chunk ----
    #pragma unroll
    for (int o = 8; o < 32; o <<= 1) {
        a0 += __shfl_xor_sync(0xffffffffu, a0, o);
        a1 += __shfl_xor_sync(0xffffffffu, a1, o);
        a2 += __shfl_xor_sync(0xffffffffu, a2, o);
        a3 += __shfl_xor_sync(0xffffffffu, a3, o);
    }
    if (lane < 8) {   // lane c holds warp-sum for m = 4c..4c+3
        ((float4*)red)[wrp * 8 + lane] = make_float4(a0, a1, a2, a3);
    }
    __syncthreads();

    // ---- warp 0: finish att, softmax, top-3 ----
    if (tid < 32) {
        float att = 0.f;
        #pragma unroll
        for (int w = 0; w < 8; w++) att += red[w * 32 + tid];

        float tl   = temp_logit[g];
        float base = 1.f / (1.f + __expf(-tl)) * 0.6f + 0.2f;
        float temp = base / (1.f + shift_mag[0]);
        float s    = att / (temp + 1e-8f);

        float mx = s;
        #pragma unroll
        for (int o = 16; o > 0; o >>= 1)
            mx = fmaxf(mx, __shfl_xor_sync(0xffffffffu, mx, o));
        float e = __expf(s - mx);
        float ssum = e;
        #pragma unroll
        for (int o = 16; o > 0; o >>= 1)
            ssum += __shfl_xor_sync(0xffffffffu, ssum, o);
        float pr = e / ssum;

        // top-3, ties -> lowest index (jax.lax.top_k semantics)
        float v  = pr;
        int   id = tid;
        #pragma unroll
        for (int k = 0; k < TK; k++) {
            float bv = v;
            int   bi = id;
            #pragma unroll
            for (int o = 16; o > 0; o >>= 1) {
                float ov = __shfl_xor_sync(0xffffffffu, bv, o);
                int   oi = __shfl_xor_sync(0xffffffffu, bi, o);
                if (ov > bv || (ov == bv && oi < bi)) { bv = ov; bi = oi; }
            }
            if (tid == 0) { bval[k] = bv; bidx[k] = bi; }
            if (id == bi) v = -INFINITY;
        }
    }
    __syncthreads();

    // ---- Pass C: gather 3 columns from W via L2 (tile just streamed through) ----
    const float v0 = bval[0], v1 = bval[1], v2 = bval[2];
    const int   i0 = bidx[0], i1 = bidx[1], i2 = bidx[2];
    const float* __restrict__ Wf = W + (size_t)g * DQ * MS;
    float* __restrict__ outg = out + (size_t)g * DQ;
    #pragma unroll
    for (int r = 0; r < 2; r++) {
        int d = tid + r * NTHREADS;
        const float* row = Wf + d * MS;
        float w0 = __ldg(row + i0);
        float w1 = __ldg(row + i1);
        float w2 = __ldg(row + i2);
        outg[d] = v0 * w0 + v1 * w1 + v2 * w2;
    }

    // ---- aux outputs (idx, vals) in tuple order after retrieved ----
    if (write_aux && tid < TK) {
        float* out_idx  = out + (size_t)NG * DQ;
        float* out_vals = out_idx + (size_t)NG * TK;
        out_idx[(size_t)g * TK + tid]  = (float)bidx[tid];
        out_vals[(size_t)g * TK + tid] = bval[tid];
    }
}

extern "C" void kernel_launch(void* const* d_in, const int* in_sizes, int n_in,
                              void* d_out, int out_size)
{
    const float* q     = (const float*)d_in[0];
    const float* W     = (const float*)d_in[1];
    const float* tl    = (const float*)d_in[2];
    const float* shift = (const float*)d_in[3];
    float* out = (float*)d_out;

    int write_aux = (out_size >= NG * DQ + 2 * NG * TK) ? 1 : 0;

    cgm_kernel<<<NG, NTHREADS>>>(q, W, tl, shift, out, write_aux);
}